// round 11
// baseline (speedup 1.0000x reference)
#include <cuda_runtime.h>
#include <cstdint>

// ---------------------------------------------------------------------------
// MemoryAttention R11: warp-specialized producer/consumer pipeline.
//   - 512 threads: warps 0-7 = GEMM (tf32 mma + ldmatrix), warps 8-15 = SELECT
//     (streaming top-32). NO per-chunk __syncthreads: mu double-buffer and a
//     3-slot score ring are synchronized purely with mbarriers.
//   - QT=64 queries/CTA, grid=128 (single wave), CT=128 centers/chunk.
//   - GEMM warp tile 16q x 64c; scores stored permuted+swizzled (verified
//     conflict-free per quarter); select decodes indices only on insert.
//   - epilogue (all 16 warps): exact fp32 rescore + softmax + gathers + gate.
// ---------------------------------------------------------------------------

#define FULLMASK 0xffffffffu

constexpr int NQ  = 8192;
constexpr int NC  = 32768;
constexpr int DK  = 64;
constexpr int QT  = 64;        // queries per CTA
constexpr int CT  = 128;       // centers per chunk
constexpr int NCHUNK = NC / CT;    // 256
constexpr int MUS  = 68;       // mu row stride (floats) inside blob
constexpr int SSTR = 132;      // score row stride
constexpr int SLOT = QT * SSTR;    // 8448 floats per score slot
constexpr int BUFFLOATS = CT + CT * MUS;      // 8832 (hm2 + mu)
constexpr uint32_t BUFBYTES = BUFFLOATS * 4;  // 35328 B

static __device__ float g_hm2[NC];
static __device__ float g_blob[(size_t)NCHUNK * BUFFLOATS];   // ~9 MB

constexpr int RV_OFF = 0;
constexpr int RE_OFF = NQ * 128;
constexpr int G_OFF  = RE_OFF + NQ * 4;

// smem layout (floats)
constexpr int OFF_MBAR = 0;                        // 10 mbarriers (<=32 f)
constexpr int OFF_BLOB = 32;                       // 2*8832 = 17664
constexpr int OFF_S    = OFF_BLOB + 2 * BUFFLOATS; // 3*8448 = 25344
constexpr int OFF_SCR  = OFF_S + 3 * SLOT;         // 16*64  = 1024
constexpr int SMEM_FLOATS = OFF_SCR + 16 * 64;     // 44064 f = 176256 B

// mbarrier slots (index * 8 bytes): 0,1 full_mu; 2,3 empty_mu;
// 4,5,6 full_sc; 7,8,9 empty_sc
__device__ __forceinline__ uint32_t to_tf32(float f) {
    uint32_t u;
    asm("cvt.rna.tf32.f32 %0, %1;" : "=r"(u) : "f"(f));
    return u;
}

__global__ void prep_kernel(const float* __restrict__ mu) {
    int c = blockIdx.x * 256 + threadIdx.x;   // 32768 rows
    const float4* r = reinterpret_cast<const float4*>(mu) + (size_t)c * 16;
    int n = c & 127;
    float* blob = g_blob + (size_t)(c >> 7) * BUFFLOATS;
    float4* w = reinterpret_cast<float4*>(blob + CT + n * MUS);
    float s = 0.f;
#pragma unroll
    for (int j = 0; j < 16; j++) {
        float4 v = r[j];
        s += v.x * v.x + v.y * v.y + v.z * v.z + v.w * v.w;
        float4 t;
        t.x = __uint_as_float(to_tf32(v.x));
        t.y = __uint_as_float(to_tf32(v.y));
        t.z = __uint_as_float(to_tf32(v.z));
        t.w = __uint_as_float(to_tf32(v.w));
        w[j] = t;
    }
    int p  = (n & 7) * 16 + (n >> 3);
    int ws = p ^ (((p >> 4) & 7) << 2);
    blob[ws] = 0.5f * s;
    g_hm2[c] = 0.5f * s;
}

__device__ __forceinline__ unsigned fenc(float f) {
    unsigned u = __float_as_uint(f);
    return (u & 0x80000000u) ? ~u : (u | 0x80000000u);
}
__device__ __forceinline__ float fdec(unsigned u) {
    return (u & 0x80000000u) ? __uint_as_float(u & 0x7fffffffu)
                             : __uint_as_float(~u);
}
__device__ __forceinline__ unsigned redux_min_u32(unsigned v) {
    unsigned r;
    asm("redux.sync.min.u32 %0, %1, 0xffffffff;" : "=r"(r) : "r"(v));
    return r;
}
__device__ __forceinline__ void mma_tf32(float* d, const uint32_t* a,
                                         uint32_t b0, uint32_t b1) {
    asm("mma.sync.aligned.m16n8k8.row.col.f32.tf32.tf32.f32 "
        "{%0,%1,%2,%3}, {%4,%5,%6,%7}, {%8,%9}, {%0,%1,%2,%3};"
        : "+f"(d[0]), "+f"(d[1]), "+f"(d[2]), "+f"(d[3])
        : "r"(a[0]), "r"(a[1]), "r"(a[2]), "r"(a[3]), "r"(b0), "r"(b1));
}
__device__ __forceinline__ void ldsm_x4(uint32_t addr, uint32_t& r0,
                                        uint32_t& r1, uint32_t& r2, uint32_t& r3) {
    asm volatile("ldmatrix.sync.aligned.m8n8.x4.shared.b16 {%0,%1,%2,%3}, [%4];"
                 : "=r"(r0), "=r"(r1), "=r"(r2), "=r"(r3) : "r"(addr));
}
__device__ __forceinline__ void mbar_init(uint32_t addr, uint32_t count) {
    asm volatile("mbarrier.init.shared.b64 [%0], %1;" :: "r"(addr), "r"(count)
                 : "memory");
}
__device__ __forceinline__ void mbar_arrive(uint32_t addr) {
    asm volatile("mbarrier.arrive.release.cta.shared.b64 _, [%0];"
                 :: "r"(addr) : "memory");
}
__device__ __forceinline__ void mbar_expect_tx(uint32_t addr, uint32_t bytes) {
    asm volatile("mbarrier.arrive.expect_tx.shared.b64 _, [%0], %1;"
                 :: "r"(addr), "r"(bytes) : "memory");
}
__device__ __forceinline__ void mbar_wait(uint32_t addr, uint32_t parity) {
    asm volatile(
        "{\n\t"
        ".reg .pred P;\n"
        "W_%=:\n\t"
        "mbarrier.try_wait.parity.acquire.cta.shared::cta.b64 P, [%0], %1, 0x989680;\n\t"
        "@P bra D_%=;\n\t"
        "bra W_%=;\n"
        "D_%=:\n\t"
        "}"
        :: "r"(addr), "r"(parity) : "memory");
}
__device__ __forceinline__ void bulk_g2s(uint32_t dst, const void* src,
                                         uint32_t bytes, uint32_t mbar) {
    asm volatile(
        "cp.async.bulk.shared::cta.global.mbarrier::complete_tx::bytes "
        "[%0], [%1], %2, [%3];"
        :: "r"(dst), "l"(src), "r"(bytes), "r"(mbar) : "memory");
}

__global__ __launch_bounds__(512, 1)
void ma_kernel(const float* __restrict__ x,
               const float* __restrict__ q_tilde,
               const float* __restrict__ g_prior,
               const float* __restrict__ mu,
               const float* __restrict__ V,
               const float* __restrict__ E,
               const float* __restrict__ sig,
               const float* __restrict__ Wg,
               const float* __restrict__ Wgb,
               const float* __restrict__ gpw,
               float* __restrict__ out) {
    extern __shared__ float sm[];
    float* sBlob = sm + OFF_BLOB;
    float* sS    = sm + OFF_S;      // 3 slots
    float* sQ    = sm + OFF_S;      // alias: Q staged in slot0 for A-frags
    float* sScr  = sm + OFF_SCR;

    const int tid  = threadIdx.x;
    const int lane = tid & 31;
    const int wid  = tid >> 5;
    const int q0   = blockIdx.x * QT;

    const uint32_t smemBase = (uint32_t)__cvta_generic_to_shared(sm);
    const uint32_t mb_full_mu  = smemBase + (OFF_MBAR * 4);
    const uint32_t mb_empty_mu = mb_full_mu + 16;
    const uint32_t mb_full_sc  = mb_full_mu + 32;
    const uint32_t mb_empty_sc = mb_full_mu + 56;
    const uint32_t sblobA = smemBase + OFF_BLOB * 4;
    const uint32_t sSA    = smemBase + OFF_S * 4;

    // ---- prologue: init barriers, stage Q ----
    if (tid == 0) {
        mbar_init(mb_full_mu, 1);      mbar_init(mb_full_mu + 8, 1);
        mbar_init(mb_empty_mu, 8);     mbar_init(mb_empty_mu + 8, 8);
#pragma unroll
        for (int s = 0; s < 3; s++) {
            mbar_init(mb_full_sc + s * 8, 8);
            mbar_init(mb_empty_sc + s * 8, 8);
        }
    }
    for (int idx = tid; idx < QT * DK; idx += 512) {
        int q = idx >> 6, k = idx & 63;
        sQ[q * MUS + k] = q_tilde[(size_t)(q0 + q) * DK + k];
    }
    __syncthreads();    // barriers + sQ visible
    if (tid == 0) {     // issue chunk 0
        mbar_expect_tx(mb_full_mu, BUFBYTES);
        bulk_g2s(sblobA, g_blob, BUFBYTES, mb_full_mu);
    }

    if (wid < 8) {
        // =================== GEMM role ===================
        const int wq = wid >> 1;    // 0..3 : rows 16wq..+15
        const int wc = wid & 1;     // 0..1 : cols 64wc..+63
        const int tr = lane >> 2, tc = lane & 3;

        uint32_t af[8][4];
        {
            const float* qa = sQ + (16 * wq + tr) * MUS + tc;
#pragma unroll
            for (int kt = 0; kt < 8; kt++) {
                af[kt][0] = to_tf32(qa[8 * kt]);
                af[kt][1] = to_tf32(qa[8 * MUS + 8 * kt]);
                af[kt][2] = to_tf32(qa[8 * kt + 4]);
                af[kt][3] = to_tf32(qa[8 * MUS + 8 * kt + 4]);
            }
        }
        __syncthreads();    // frag reads done before slot0 score stores

        // ldmatrix base offset (bytes) inside blob's mu section, np=0
        const uint32_t boff = (uint32_t)(CT * 4) +
            (uint32_t)(((64 * wc + ((lane >> 4) & 1) * 8 + (lane & 7)) * MUS
                        + ((lane >> 3) & 1) * 4) * 4);

        // score/hm2 quad word offsets (per-thread constants)
        int qw[2][2];   // [u][quad]
#pragma unroll
        for (int u = 0; u < 2; u++) {
            int e = 2 * tc + u, X = 16 * e + 8 * wc, fe = 4 * e;
            qw[u][0] = X ^ fe;
            qw[u][1] = (X + 4) ^ fe;
        }
        const int rowlo = (16 * wq + tr) * SSTR;
        const int rowhi = rowlo + 8 * SSTR;

        for (int ch = 0; ch < NCHUNK; ++ch) {
            const int buf = ch & 1;
            mbar_wait(mb_full_mu + buf * 8, (ch >> 1) & 1);

            if (tid == 0 && ch + 1 < NCHUNK) {
                int nb = (ch + 1) & 1;
                if (ch + 1 >= 2)
                    mbar_wait(mb_empty_mu + nb * 8, (((ch + 1) >> 1) - 1) & 1);
                mbar_expect_tx(mb_full_mu + nb * 8, BUFBYTES);
                bulk_g2s(sblobA + (uint32_t)nb * BUFBYTES,
                         g_blob + (size_t)(ch + 1) * BUFFLOATS, BUFBYTES,
                         mb_full_mu + nb * 8);
            }

            const uint32_t bufB = sblobA + (uint32_t)buf * BUFBYTES;
            const float*   hbp  = sBlob + buf * BUFFLOATS;

            float acc[8][4];
#pragma unroll
            for (int nt = 0; nt < 8; nt++)
#pragma unroll
                for (int j = 0; j < 4; j++) acc[nt][j] = 0.f;

#pragma unroll
            for (int kt = 0; kt < 8; kt++) {
#pragma unroll
                for (int np = 0; np < 4; np++) {
                    uint32_t r0, r1, r2, r3;
                    ldsm_x4(bufB + boff + (uint32_t)(np * (16 * MUS * 4) + kt * 32),
                            r0, r1, r2, r3);
                    mma_tf32(acc[2 * np],     af[kt], r0, r1);
                    mma_tf32(acc[2 * np + 1], af[kt], r2, r3);
                }
            }

            // wait for score slot credit, then store scores
            const int slot = ch % 3;
            if (ch >= 3)
                mbar_wait(mb_empty_sc + slot * 8, ((ch / 3) - 1) & 1);

            float* sb = sS + slot * SLOT;
#pragma unroll
            for (int u = 0; u < 2; u++) {
                float4 hA = *reinterpret_cast<const float4*>(hbp + qw[u][0]);
                float4 hB = *reinterpret_cast<const float4*>(hbp + qw[u][1]);
#pragma unroll
                for (int rh = 0; rh < 2; rh++) {
                    int j = 2 * rh + u;
                    int rb = rh ? rowhi : rowlo;
                    float4 v;
                    v.x = acc[0][j] - hA.x; v.y = acc[1][j] - hA.y;
                    v.z = acc[2][j] - hA.z; v.w = acc[3][j] - hA.w;
                    *reinterpret_cast<float4*>(sb + rb + qw[u][0]) = v;
                    v.x = acc[4][j] - hB.x; v.y = acc[5][j] - hB.y;
                    v.z = acc[6][j] - hB.z; v.w = acc[7][j] - hB.w;
                    *reinterpret_cast<float4*>(sb + rb + qw[u][1]) = v;
                }
            }
            if (lane == 0) {
                mbar_arrive(mb_full_sc + slot * 8);
                mbar_arrive(mb_empty_mu + buf * 8);
            }
        }
    } else {
        // =================== SELECT role ===================
        __syncthreads();    // matches GEMM's post-frag barrier
        const int sel = wid - 8;
        const int qb  = 8 * sel;    // owns queries qb..qb+7

        unsigned cu[8]; int ci[8]; float thr[8]; unsigned thrU[8];
        const unsigned NEGINF_U = fenc(-INFINITY);
#pragma unroll
        for (int r = 0; r < 8; r++) {
            cu[r] = NEGINF_U; ci[r] = 0; thr[r] = -INFINITY; thrU[r] = NEGINF_U;
        }

        for (int ch = 0; ch < NCHUNK; ++ch) {
            const int slot = ch % 3;
            mbar_wait(mb_full_sc + slot * 8, (ch / 3) & 1);
            const float* sb = sS + slot * SLOT;
            const int base = ch * CT;

            float4 f[8]; float lmax[8];
#pragma unroll
            for (int r = 0; r < 8; r++) {
                f[r] = *reinterpret_cast<const float4*>(
                           sb + (qb + r) * SSTR + 4 * lane);
                lmax[r] = fmaxf(fmaxf(f[r].x, f[r].y), fmaxf(f[r].z, f[r].w));
            }
            bool anyc = false;
#pragma unroll
            for (int r = 0; r < 8; r++) anyc |= (lmax[r] > thr[r]);
            if (__ballot_sync(FULLMASK, anyc)) {
#pragma unroll
                for (int r = 0; r < 8; r++) {
                    unsigned m = __ballot_sync(FULLMASK, lmax[r] > thr[r]);
                    while (m) {
                        int src = __ffs(m) - 1;
                        m &= m - 1;
                        float g0 = __shfl_sync(FULLMASK, f[r].x, src);
                        float g1 = __shfl_sync(FULLMASK, f[r].y, src);
                        float g2 = __shfl_sync(FULLMASK, f[r].z, src);
                        float g3 = __shfl_sync(FULLMASK, f[r].w, src);
                        // decode: e=(src>>2)^(src>>4); p=(4src^4e)+j;
                        // n = ((p&15)<<3)|(p>>4)
                        int pb = (4 * src) ^ (4 * ((src >> 2) ^ (src >> 4)));
#pragma unroll
                        for (int j = 0; j < 4; j++) {
                            float nv = (j == 0) ? g0 : (j == 1) ? g1
                                      : (j == 2) ? g2 : g3;
                            if (nv > thr[r]) {
                                unsigned bl = __ballot_sync(FULLMASK,
                                                            cu[r] == thrU[r]);
                                int ml = __ffs(bl) - 1;
                                if (lane == ml) {
                                    cu[r] = fenc(nv);
                                    int p = pb + j;
                                    ci[r] = base + (((p & 15) << 3) | (p >> 4));
                                }
                                thrU[r] = redux_min_u32(cu[r]);
                                thr[r]  = fdec(thrU[r]);
                            }
                        }
                    }
                }
            }
            if (lane == 0) mbar_arrive(mb_empty_sc + slot * 8);
        }

        // publish top-32 indices into own rows of slot0 (sTopI[q] at q*SSTR)
        int* sTopI = reinterpret_cast<int*>(sS);
#pragma unroll
        for (int r = 0; r < 8; r++)
            sTopI[(qb + r) * SSTR + lane] = ci[r];
    }

    __syncthreads();    // all roles done; sTopI visible

    const int* sTopI = reinterpret_cast<const int*>(sS);
    const float sigma  = sig[0];
    const float inv_s2 = 1.f / (sigma * sigma);
    const float bgate  = Wgb[0];
    const float gw     = gpw[0];

    float* myW = sScr + wid * 64;
    int*   myI = reinterpret_cast<int*>(myW + 32);

    // ---- epilogue: EXACT rescore + softmax + gathers + gate (16 warps) ----
    for (int round = 0; round < 4; ++round) {
        int q   = wid + 16 * round;
        int qg2 = q0 + q;

        int idx = sTopI[q * SSTR + lane];

        const float4* mrow = reinterpret_cast<const float4*>(mu + (size_t)idx * DK);
        const float4* qrow = reinterpret_cast<const float4*>(q_tilde + (size_t)qg2 * DK);
        float d0 = 0.f, d1 = 0.f, d2 = 0.f, d3 = 0.f;
#pragma unroll
        for (int j = 0; j < 16; j += 4) {
            float4 m0 = mrow[j],     qv0 = qrow[j];
            float4 m1 = mrow[j + 1], qv1 = qrow[j + 1];
            float4 m2 = mrow[j + 2], qv2 = qrow[j + 2];
            float4 m3 = mrow[j + 3], qv3 = qrow[j + 3];
            d0 += m0.x * qv0.x + m0.y * qv0.y + m0.z * qv0.z + m0.w * qv0.w;
            d1 += m1.x * qv1.x + m1.y * qv1.y + m1.z * qv1.z + m1.w * qv1.w;
            d2 += m2.x * qv2.x + m2.y * qv2.y + m2.z * qv2.z + m2.w * qv2.w;
            d3 += m3.x * qv3.x + m3.y * qv3.y + m3.z * qv3.z + m3.w * qv3.w;
        }
        float s = ((d0 + d1) + (d2 + d3) - g_hm2[idx]) * inv_s2;

        float mx = s;
#pragma unroll
        for (int off = 16; off; off >>= 1)
            mx = fmaxf(mx, __shfl_xor_sync(FULLMASK, mx, off));
        float e = __expf(s - mx);
        float se = e;
#pragma unroll
        for (int off = 16; off; off >>= 1)
            se += __shfl_xor_sync(FULLMASK, se, off);
        float wgt = e / se;

        myW[lane] = wgt;
        myI[lane] = idx;
        __syncwarp();

        float4 acc = make_float4(0.f, 0.f, 0.f, 0.f);
#pragma unroll 4
        for (int k = 0; k < 32; k++) {
            float wk = myW[k];
            size_t row = (size_t)myI[k];
            float4 v = reinterpret_cast<const float4*>(V + row * 128)[lane];
            acc.x += wk * v.x; acc.y += wk * v.y;
            acc.z += wk * v.z; acc.w += wk * v.w;
        }

        float re = 0.f;
        if (lane < 4) {
            for (int k = 0; k < 32; k++)
                re += myW[k] * E[(size_t)myI[k] * 4 + lane];
        }

        const float4 wv = reinterpret_cast<const float4*>(Wg + 256)[lane];
        float tot = acc.x * wv.x + acc.y * wv.y + acc.z * wv.z + acc.w * wv.w;
        const float* xq = x + (size_t)qg2 * 256;
#pragma unroll
        for (int u = 0; u < 8; u++) {
            int t = lane + 32 * u;
            tot += xq[t] * Wg[t];
        }
#pragma unroll
        for (int off = 16; off; off >>= 1)
            tot += __shfl_xor_sync(FULLMASK, tot, off);

        reinterpret_cast<float4*>(out + RV_OFF + (size_t)qg2 * 128)[lane] = acc;
        if (lane < 4) out[RE_OFF + (size_t)qg2 * 4 + lane] = re;
        if (lane == 0) {
            float z = tot + bgate + gw * g_prior[qg2];
            out[G_OFF + qg2] = 1.f / (1.f + __expf(-z));
        }
        __syncwarp();
    }
}

extern "C" void kernel_launch(void* const* d_in, const int* in_sizes, int n_in,
                              void* d_out, int out_size) {
    (void)in_sizes; (void)n_in; (void)out_size;
    const float* x   = (const float*)d_in[0];
    const float* qt  = (const float*)d_in[1];
    const float* gp  = (const float*)d_in[2];
    const float* mu  = (const float*)d_in[3];
    const float* V   = (const float*)d_in[4];
    const float* E   = (const float*)d_in[5];
    const float* sg  = (const float*)d_in[6];
    const float* Wg  = (const float*)d_in[7];
    const float* Wb  = (const float*)d_in[8];
    const float* gw  = (const float*)d_in[9];

    prep_kernel<<<NC / 256, 256>>>(mu);

    const int smem_bytes = SMEM_FLOATS * 4;   // 176256
    cudaFuncSetAttribute(ma_kernel, cudaFuncAttributeMaxDynamicSharedMemorySize,
                         smem_bytes);
    ma_kernel<<<NQ / QT, 512, smem_bytes>>>(x, qt, gp, mu, V, E, sg, Wg, Wb, gw,
                                            (float*)d_out);
}